// round 1
// baseline (speedup 1.0000x reference)
#include <cuda_runtime.h>

// Problem constants
#define kB 16
#define kL 1444
#define kD 128
#define kC 21
#define kChunks 38
#define kCL 38          // 38 * 38 == 1444 exactly

// Device scratch (no allocations allowed)
__device__ float g_chunkSums[kB * kChunks * kC * kD]; // per-chunk class sums -> exclusive prefix after scan
__device__ float g_tot[kB * kC * kD];                 // total class sums per batch
__device__ float g_R[kB * kC * kD];                   // R[b][a][d] = sum_c P[c][a] * Tot[b][c][d]
__device__ float g_Q[kC * kC];                        // Q[a][c] = P[a][c] - P[c][a]
__device__ float g_coef[kC];                          // (a!=0) - P[a][a]
__device__ int   g_cls[kB * kL];                      // class idx as int32
__device__ int   g_is64;                              // dtype detection flag

// ---------------------------------------------------------------------------
// Detect whether class_idx buffer is int64 or int32.
// If int32, reading as int64 packs two class values (0..20); high word is a
// class value that is nonzero with prob ~20/21 per element -> any value > 20
// when read as int64 implies int32 layout. Scans up to 2048 words (always
// within buffer bounds in both layouts since we pass n/2 words).
__global__ void detect_kernel(const long long* __restrict__ p, int n64) {
    __shared__ int bad;
    if (threadIdx.x == 0) bad = 0;
    __syncthreads();
    int lim = n64 < 2048 ? n64 : 2048;
    int local = 0;
    for (int i = threadIdx.x; i < lim; i += blockDim.x) {
        unsigned long long v = (unsigned long long)p[i];
        if (v > 20ULL) local = 1;
    }
    if (local) atomicOr(&bad, 1);
    __syncthreads();
    if (threadIdx.x == 0) g_is64 = bad ? 0 : 1;
}

__global__ void convert_kernel(const void* __restrict__ p, int n) {
    int i = blockIdx.x * blockDim.x + threadIdx.x;
    if (i >= n) return;
    int v;
    if (g_is64) v = (int)((const long long*)p)[i];
    else        v = ((const int*)p)[i];
    g_cls[i] = v;
}

// ---------------------------------------------------------------------------
// Q and coef from P
__global__ void prep_kernel(const float* __restrict__ P) {
    int t = threadIdx.x;
    if (t < kC * kC) {
        int a = t / kC, c = t % kC;
        g_Q[t] = P[a * kC + c] - P[c * kC + a];
    }
    if (t < kC) {
        g_coef[t] = (t != 0 ? 1.0f : 0.0f) - P[t * kC + t];
    }
}

// ---------------------------------------------------------------------------
// Per-chunk class-partitioned sums. One CTA per (chunk, batch); thread = d.
__global__ void __launch_bounds__(kD) chunksum_kernel(const float* __restrict__ src) {
    int d = threadIdx.x;
    int chunk = blockIdx.x, b = blockIdx.y;

    __shared__ float acc[kC * kD];
    __shared__ int clsS[kCL];

    #pragma unroll
    for (int c = 0; c < kC; c++) acc[c * kD + d] = 0.0f;
    if (d < kCL) clsS[d] = g_cls[b * kL + chunk * kCL + d];
    __syncthreads();

    const float* sp = src + ((size_t)b * kL + (size_t)chunk * kCL) * kD + d;
    for (int i = 0; i < kCL; i++) {
        acc[clsS[i] * kD + d] += sp[(size_t)i * kD];
    }

    float* outp = g_chunkSums + (((size_t)b * kChunks + chunk) * kC) * kD + d;
    #pragma unroll
    for (int c = 0; c < kC; c++) outp[(size_t)c * kD] = acc[c * kD + d];
}

// ---------------------------------------------------------------------------
// Exclusive scan over chunks for one (b, c); writes totals.
__global__ void __launch_bounds__(kD) scan_kernel() {
    int d = threadIdx.x;
    int c = blockIdx.x, b = blockIdx.y;
    float run = 0.0f;
    float* base = g_chunkSums + (((size_t)b * kChunks) * kC + c) * kD + d;
    #pragma unroll
    for (int k = 0; k < kChunks; k++) {
        float t = base[(size_t)k * kC * kD];
        base[(size_t)k * kC * kD] = run;
        run += t;
    }
    g_tot[((size_t)b * kC + c) * kD + d] = run;
}

// R[b][a][d] = sum_c P[c][a] * Tot[b][c][d]
__global__ void __launch_bounds__(kD) rmat_kernel(const float* __restrict__ P) {
    int d = threadIdx.x;
    int a = blockIdx.x, b = blockIdx.y;
    float r = 0.0f;
    #pragma unroll
    for (int c = 0; c < kC; c++)
        r = fmaf(P[c * kC + a], g_tot[((size_t)b * kC + c) * kD + d], r);
    g_R[((size_t)b * kC + a) * kD + d] = r;
}

// ---------------------------------------------------------------------------
// Main: fused[i] = Q[c_i,:]·pre + R[c_i] + coef[c_i]*src[i]; pre[c_i] += src[i].
// One CTA per (chunk, batch). Thread d keeps pre[21] in registers.
__global__ void __launch_bounds__(kD) main_kernel(const float* __restrict__ src,
                                                  float* __restrict__ outF,
                                                  float* __restrict__ outS) {
    int d = threadIdx.x;
    int chunk = blockIdx.x, b = blockIdx.y;

    __shared__ float Rsh[kC * kD];
    __shared__ float Qsh[kC * kC];
    __shared__ float coefS[kC];
    __shared__ int clsS[kCL];

    for (int t = d; t < kC * kC; t += kD) Qsh[t] = g_Q[t];
    if (d < kC) coefS[d] = g_coef[d];
    if (d < kCL) clsS[d] = g_cls[b * kL + chunk * kCL + d];
    #pragma unroll
    for (int c = 0; c < kC; c++)
        Rsh[c * kD + d] = g_R[((size_t)b * kC + c) * kD + d];

    float pre[kC];
    const float* cb = g_chunkSums + (((size_t)b * kChunks + chunk) * kC) * kD + d;
    #pragma unroll
    for (int c = 0; c < kC; c++) pre[c] = cb[(size_t)c * kD];
    __syncthreads();

    size_t off = ((size_t)b * kL + (size_t)chunk * kCL) * kD + d;
    const float* sp = src + off;
    float* fp = outF + off;
    float* op = (outS != nullptr) ? (outS + off) : nullptr;

    for (int i = 0; i < kCL; i++) {
        int c = clsS[i];                 // warp-uniform
        float s = sp[(size_t)i * kD];

        float a0 = Rsh[c * kD + d];
        float a1 = coefS[c] * s;
        float a2 = 0.0f;
        const float* qrow = Qsh + c * kC;
        #pragma unroll
        for (int cc = 0; cc < kC; cc++) {
            float q = qrow[cc];
            if ((cc % 3) == 0)      a0 = fmaf(q, pre[cc], a0);
            else if ((cc % 3) == 1) a1 = fmaf(q, pre[cc], a1);
            else                    a2 = fmaf(q, pre[cc], a2);
        }
        // exclusive prefix update (after use)
        #pragma unroll
        for (int cc = 0; cc < kC; cc++)
            if (cc == c) pre[cc] += s;

        fp[(size_t)i * kD] = (a0 + a1) + a2;
        if (op) op[(size_t)i * kD] = s;
    }
}

// ---------------------------------------------------------------------------
extern "C" void kernel_launch(void* const* d_in, const int* in_sizes, int n_in,
                              void* d_out, int out_size) {
    const float* P   = (const float*)d_in[0];  // cls_r_prob [C,C]
    const float* src = (const float*)d_in[1];  // source [B,L,D]
    const void*  cls = d_in[2];                // class_idx [B,L] (int64 or int32)

    float* outF = (float*)d_out;
    const long long fusedElems = (long long)kB * kL * kD;
    float* outS = ((long long)out_size >= 2 * fusedElems) ? (outF + fusedElems) : nullptr;

    const int n = kB * kL;
    detect_kernel<<<1, 256>>>((const long long*)cls, n / 2);
    convert_kernel<<<(n + 255) / 256, 256>>>(cls, n);
    prep_kernel<<<1, 512>>>(P);
    chunksum_kernel<<<dim3(kChunks, kB), kD>>>(src);
    scan_kernel<<<dim3(kC, kB), kD>>>();
    rmat_kernel<<<dim3(kC, kB), kD>>>(P);
    main_kernel<<<dim3(kChunks, kB), kD>>>(src, outF, outS);
}

// round 2
// speedup vs baseline: 1.0750x; 1.0750x over previous
#include <cuda_runtime.h>

#define kB 16
#define kL 1444
#define kD 128
#define kD2 64          // float2 lanes per position
#define kC 21
#define kChunks 38
#define kCL 38          // 38*38 == 1444
#define kGrid (kB*kChunks)   // 608 CTAs
#define kT 64
#define kQPAD 22        // padded row stride for Q/Pt tables

typedef unsigned long long ull;

// Device scratch (no allocations allowed)
__device__ float g_cs[kB*kChunks*kC*kD];   // per-chunk class sums -> exclusive prefix after scan
__device__ float g_tot[kB*kC*kD];          // per-batch class totals
__device__ unsigned g_bar0, g_bar1;        // grid barrier counters

// ---- packed f32x2 helpers (Blackwell) -------------------------------------
static __device__ __forceinline__ ull fadd2(ull a, ull b){
    ull r; asm("add.rn.f32x2 %0,%1,%2;" : "=l"(r) : "l"(a), "l"(b)); return r;
}
static __device__ __forceinline__ ull ffma2x(ull a, ull b, ull c){
    ull r; asm("fma.rn.f32x2 %0,%1,%2,%3;" : "=l"(r) : "l"(a), "l"(b), "l"(c)); return r;
}
static __device__ __forceinline__ ull dup2(float x){
    ull r; asm("mov.b64 %0,{%1,%1};" : "=l"(r) : "f"(x)); return r;
}
static __device__ __forceinline__ ull ldcg64(const float* p){
    ull r; asm volatile("ld.global.cg.b64 %0,[%1];" : "=l"(r) : "l"(p)); return r;
}
static __device__ __forceinline__ void stcg64(float* p, ull v){
    asm volatile("st.global.cg.b64 [%0],%1;" :: "l"(p), "l"(v));
}

// ---- barrier reset (launched before persistent kernel each call) ----------
__global__ void reset_kernel(){ g_bar0 = 0u; g_bar1 = 0u; }

// ---- grid-wide barrier (all 608 CTAs resident by construction) ------------
static __device__ __forceinline__ void gridbar(unsigned* bar){
    __syncthreads();
    if (threadIdx.x == 0){
        __threadfence();
        unsigned prev = atomicAdd(bar, 1u);
        if (prev + 1u < (unsigned)kGrid){
            while (*((volatile unsigned*)bar) < (unsigned)kGrid) __nanosleep(128);
        }
        __threadfence();
    }
    __syncthreads();
}

// ---------------------------------------------------------------------------
// One persistent kernel, 3 phases separated by grid barriers.
// CTA = (chunk, b); thread t owns d-pair (2t, 2t+1).
__global__ void __launch_bounds__(kT, 5) relation_kernel(
    const float* __restrict__ P, const float* __restrict__ src,
    const void* __restrict__ cls, float* __restrict__ outF,
    float* __restrict__ outS)
{
    __shared__ ull Q2[kC*kQPAD];     // dup(P[a][c]-P[c][a])
    __shared__ ull Pt2[kC*kQPAD];    // dup(P[c][a]) indexed [a][c]
    __shared__ ull coef2[kC];        // dup((a!=0)-P[a][a])
    __shared__ int clsS[kCL];
    __shared__ ull dotL[kCL*kD2];    // intra-chunk dot, per position
    __shared__ ull dotA[kC*kD2];     // per-class combined vector

    const int t = threadIdx.x;
    const int chunk = blockIdx.x, b = blockIdx.y;

    // --- build lane-duplicated tables ---
    for (int idx = t; idx < kC*kC; idx += kT){
        int a = idx / kC, c = idx % kC;
        float pac = P[a*kC + c], pca = P[c*kC + a];
        Q2 [a*kQPAD + c] = dup2(pac - pca);
        Pt2[a*kQPAD + c] = dup2(pca);
    }
    if (t < kC) coef2[t] = dup2((t != 0 ? 1.0f : 0.0f) - P[t*kC + t]);

    // --- int64/int32 class-index layout detection (consistent across CTAs) ---
    int bad = 0;
    {
        const ull* p64 = (const ull*)cls;
        for (int i = t; i < 1024; i += kT)
            if (p64[i] > 20ULL) bad = 1;   // impossible under int64 layout
    }
    int is32 = __syncthreads_or(bad);      // also syncs table builds

    const int posBase = b*kL + chunk*kCL;
    if (t < kCL)
        clsS[t] = is32 ? ((const int*)cls)[posBase + t]
                       : (int)((const long long*)cls)[posBase + t];
    __syncthreads();

    // ================= phase 0: intra-chunk dot + class sums + src copy ====
    ull pre2[kC];
    #pragma unroll
    for (int c = 0; c < kC; c++) pre2[c] = 0ULL;

    const ull* sp = (const ull*)src + (size_t)posBase*kD2 + t;
    ull* osp = outS ? ((ull*)outS + (size_t)posBase*kD2 + t) : (ull*)0;

    for (int i = 0; i < kCL; i++){
        int c = clsS[i];                        // warp-uniform
        ull s2 = sp[(size_t)i*kD2];
        if (osp) osp[(size_t)i*kD2] = s2;       // source passthrough output

        const ull* qrow = Q2 + (size_t)c*kQPAD;
        ull a0 = 0ULL, a1 = 0ULL, a2 = 0ULL;
        #pragma unroll
        for (int j = 0; j < 7; j++){
            a0 = ffma2x(qrow[3*j+0], pre2[3*j+0], a0);
            a1 = ffma2x(qrow[3*j+1], pre2[3*j+1], a1);
            a2 = ffma2x(qrow[3*j+2], pre2[3*j+2], a2);
        }
        dotL[i*kD2 + t] = fadd2(fadd2(a0, a1), a2);

        #pragma unroll
        for (int cc = 0; cc < kC; cc++)
            if (cc == c) pre2[cc] = fadd2(pre2[cc], s2);
    }

    {   // write inclusive chunk sums
        float* cs = g_cs + ((size_t)(b*kChunks + chunk)*kC)*kD + 2*t;
        #pragma unroll
        for (int c = 0; c < kC; c++) stcg64(cs + (size_t)c*kD, pre2[c]);
    }

    gridbar(&g_bar0);

    // ================= phase 1: exclusive scan over chunks (336 units) =====
    {
        int id = b*kChunks + chunk;
        if (id < kB*kC){
            int bb = id / kC, c = id % kC;
            float* p0 = g_cs + ((size_t)bb*kChunks*kC + c)*kD + 2*t;
            const size_t stride = (size_t)kC*kD;
            ull v[kChunks];
            #pragma unroll
            for (int k = 0; k < kChunks; k++) v[k] = ldcg64(p0 + k*stride);
            ull run = 0ULL;
            #pragma unroll
            for (int k = 0; k < kChunks; k++){
                stcg64(p0 + k*stride, run);    // exclusive prefix in place
                run = fadd2(run, v[k]);
            }
            stcg64(g_tot + ((size_t)bb*kC + c)*kD + 2*t, run);
        }
    }

    gridbar(&g_bar1);

    // ================= phase 2: per-class vectors + final combine ==========
    ull base2[kC], tot2[kC];
    {
        const float* csr  = g_cs  + ((size_t)(b*kChunks + chunk)*kC)*kD + 2*t;
        const float* totr = g_tot + ((size_t)b*kC)*kD + 2*t;
        #pragma unroll
        for (int c = 0; c < kC; c++) base2[c] = ldcg64(csr  + (size_t)c*kD);
        #pragma unroll
        for (int c = 0; c < kC; c++) tot2[c]  = ldcg64(totr + (size_t)c*kD);
    }

    // dotA[a] = sum_c Q[a,c]*base[c] + sum_c P[c,a]*tot[c]
    for (int a = 0; a < kC; a++){
        const ull* qrow = Q2  + (size_t)a*kQPAD;
        const ull* prow = Pt2 + (size_t)a*kQPAD;
        ull acc0 = 0ULL, acc1 = 0ULL;
        #pragma unroll
        for (int c = 0; c < kC; c++){
            acc0 = ffma2x(qrow[c], base2[c], acc0);
            acc1 = ffma2x(prow[c], tot2[c],  acc1);
        }
        dotA[a*kD2 + t] = fadd2(acc0, acc1);
    }

    {   // fused[i] = dotLocal[i] + dotA[c_i] + coef[c_i]*s_i
        const ull* sp2 = (const ull*)src + (size_t)posBase*kD2 + t;
        ull* fp = (ull*)outF + (size_t)posBase*kD2 + t;
        for (int i = 0; i < kCL; i++){
            int c = clsS[i];
            ull s2 = sp2[(size_t)i*kD2];
            ull r = fadd2(dotL[i*kD2 + t], dotA[c*kD2 + t]);
            r = ffma2x(coef2[c], s2, r);
            fp[(size_t)i*kD2] = r;
        }
    }
}

// ---------------------------------------------------------------------------
extern "C" void kernel_launch(void* const* d_in, const int* in_sizes, int n_in,
                              void* d_out, int out_size)
{
    const float* P   = (const float*)d_in[0];  // cls_r_prob [C,C]
    const float* src = (const float*)d_in[1];  // source [B,L,D]
    const void*  cls = d_in[2];                // class_idx [B,L]

    float* outF = (float*)d_out;
    const long long fusedElems = (long long)kB*kL*kD;
    float* outS = ((long long)out_size >= 2*fusedElems) ? (outF + fusedElems) : nullptr;

    reset_kernel<<<1, 1>>>();
    relation_kernel<<<dim3(kChunks, kB), kT>>>(P, src, cls, outF, outS);
}

// round 3
// speedup vs baseline: 1.1301x; 1.0512x over previous
#include <cuda_runtime.h>

#define kB 16
#define kL 1444
#define kD 128
#define kD2 64          // float2 lanes per position
#define kC 21
#define kChunks 76
#define kCL 19          // 76*19 == 1444
#define kT 64
#define kQPAD 22
#define kWaves 4        // 76 = 4*19 scan waves

typedef unsigned long long ull;

// Device scratch (no allocations allowed)
__device__ float g_cs[kB*kChunks*kC*kD];   // chunk class sums -> exclusive prefix after K2
__device__ float g_tot[kB*kC*kD];          // per-batch class totals
__device__ float g_R[kB*kC*kD];            // R[b][a][d] = sum_c P[c][a]*tot[b][c][d]
__device__ int   g_cls[kB*kL];             // class idx as int32
__device__ unsigned g_cnt[kB];             // per-batch arrival counters (self-resetting)

// ---- packed f32x2 helpers (Blackwell) -------------------------------------
static __device__ __forceinline__ ull fadd2(ull a, ull b){
    ull r; asm("add.rn.f32x2 %0,%1,%2;" : "=l"(r) : "l"(a), "l"(b)); return r;
}
static __device__ __forceinline__ ull ffma2x(ull a, ull b, ull c){
    ull r; asm("fma.rn.f32x2 %0,%1,%2,%3;" : "=l"(r) : "l"(a), "l"(b), "l"(c)); return r;
}
static __device__ __forceinline__ ull dup2(float x){
    ull r; asm("mov.b64 %0,{%1,%1};" : "=l"(r) : "f"(x)); return r;
}
static __device__ __forceinline__ ull ldcg64(const float* p){
    ull r; asm volatile("ld.global.cg.b64 %0,[%1];" : "=l"(r) : "l"(p)); return r;
}
static __device__ __forceinline__ void stcg64(float* p, ull v){
    asm volatile("st.global.cg.b64 [%0],%1;" :: "l"(p), "l"(v));
}

// ===========================================================================
// K1: per-chunk class sums (registers), source passthrough, idx conversion.
// CTA = (chunk, b), thread t owns d-pair (2t, 2t+1).
__global__ void __launch_bounds__(kT) sum_kernel(const float* __restrict__ src,
                                                 const void*  __restrict__ cls,
                                                 float* __restrict__ outS)
{
    const int t = threadIdx.x;
    const int chunk = blockIdx.x, b = blockIdx.y;

    // int64/int32 layout detection (first 512 words; any value>20 => int32)
    int bad = 0;
    {
        const ull* p64 = (const ull*)cls;
        for (int i = t; i < 512; i += kT)
            if (p64[i] > 20ULL) bad = 1;
    }
    int is32 = __syncthreads_or(bad);

    __shared__ int clsS[kCL];
    const int posBase = b*kL + chunk*kCL;
    if (t < kCL){
        int v = is32 ? ((const int*)cls)[posBase + t]
                     : (int)((const long long*)cls)[posBase + t];
        clsS[t] = v;
        g_cls[posBase + t] = v;
    }
    __syncthreads();

    const ull* sp = (const ull*)src + (size_t)posBase*kD2 + t;
    ull* osp = outS ? ((ull*)outS + (size_t)posBase*kD2 + t) : (ull*)0;

    ull s[kCL];
    #pragma unroll
    for (int i = 0; i < kCL; i++) s[i] = sp[(size_t)i*kD2];
    if (osp){
        #pragma unroll
        for (int i = 0; i < kCL; i++) osp[(size_t)i*kD2] = s[i];
    }

    ull pre[kC];
    #pragma unroll
    for (int c = 0; c < kC; c++) pre[c] = 0ULL;

    #pragma unroll
    for (int i = 0; i < kCL; i++){
        int c = clsS[i];
        #pragma unroll
        for (int cc = 0; cc < kC; cc++)
            if (cc == c) pre[cc] = fadd2(pre[cc], s[i]);
    }

    float* cs = g_cs + ((size_t)(b*kChunks + chunk)*kC)*kD + 2*t;
    #pragma unroll
    for (int c = 0; c < kC; c++) stcg64(cs + (size_t)c*kD, pre[c]);
}

// ===========================================================================
// K2: exclusive scan over chunks per (b,c); last CTA of each batch computes R.
__global__ void __launch_bounds__(kT) scan_kernel(const float* __restrict__ P)
{
    const int t = threadIdx.x;
    const int id = blockIdx.x;
    const int b = id / kC, c = id % kC;

    float* base = g_cs + ((size_t)b*kChunks*kC + c)*kD + 2*t;
    const size_t stride = (size_t)kC*kD;

    ull run = 0ULL;
    #pragma unroll
    for (int w = 0; w < kWaves; w++){
        ull v[kCL];
        #pragma unroll
        for (int k = 0; k < kCL; k++) v[k] = ldcg64(base + (size_t)(w*kCL + k)*stride);
        #pragma unroll
        for (int k = 0; k < kCL; k++){
            stcg64(base + (size_t)(w*kCL + k)*stride, run);
            run = fadd2(run, v[k]);
        }
    }
    stcg64(g_tot + ((size_t)b*kC + c)*kD + 2*t, run);

    __threadfence();
    __shared__ int isLast;
    if (t == 0){
        unsigned old = atomicAdd(&g_cnt[b], 1u);
        isLast = (old == (unsigned)(kC - 1));
    }
    __syncthreads();

    if (isLast){
        __threadfence();
        __shared__ float Psh[kC*kC];
        for (int i = t; i < kC*kC; i += kT) Psh[i] = P[i];

        ull tot2[kC];
        #pragma unroll
        for (int cc = 0; cc < kC; cc++)
            tot2[cc] = ldcg64(g_tot + ((size_t)b*kC + cc)*kD + 2*t);
        __syncthreads();

        #pragma unroll
        for (int a = 0; a < kC; a++){
            ull acc = 0ULL;
            #pragma unroll
            for (int cc = 0; cc < kC; cc++)
                acc = ffma2x(dup2(Psh[cc*kC + a]), tot2[cc], acc);
            stcg64(g_R + ((size_t)b*kC + a)*kD + 2*t, acc);
        }
        if (t == 0) g_cnt[b] = 0u;   // self-reset for graph replay
    }
}

// ===========================================================================
// K3: fused[i] = Q[c_i,:]·pre(i) + R[c_i] + coef[c_i]*s_i ; pre[c_i] += s_i.
__global__ void __launch_bounds__(kT) main_kernel(const float* __restrict__ P,
                                                  const float* __restrict__ src,
                                                  float* __restrict__ outF)
{
    const int t = threadIdx.x;
    const int chunk = blockIdx.x, b = blockIdx.y;

    __shared__ ull Q2[kC*kQPAD];     // dup(P[a][c]-P[c][a])
    __shared__ ull coef2[kC];
    __shared__ ull Rsh[kC*kD2];
    __shared__ int clsS[kCL];

    for (int idx = t; idx < kC*kC; idx += kT){
        int a = idx / kC, c = idx % kC;
        Q2[a*kQPAD + c] = dup2(P[a*kC + c] - P[c*kC + a]);
    }
    if (t < kC) coef2[t] = dup2((t != 0 ? 1.0f : 0.0f) - P[t*kC + t]);

    const int posBase = b*kL + chunk*kCL;
    if (t < kCL) clsS[t] = g_cls[posBase + t];

    #pragma unroll
    for (int a = 0; a < kC; a++)
        Rsh[a*kD2 + t] = ldcg64(g_R + ((size_t)b*kC + a)*kD + 2*t);

    ull pre[kC];
    {
        const float* cs = g_cs + ((size_t)(b*kChunks + chunk)*kC)*kD + 2*t;
        #pragma unroll
        for (int c = 0; c < kC; c++) pre[c] = ldcg64(cs + (size_t)c*kD);
    }
    __syncthreads();

    const ull* sp = (const ull*)src + (size_t)posBase*kD2 + t;
    ull* fp = (ull*)outF + (size_t)posBase*kD2 + t;

    ull s[kCL];
    #pragma unroll
    for (int i = 0; i < kCL; i++) s[i] = sp[(size_t)i*kD2];

    #pragma unroll
    for (int i = 0; i < kCL; i++){
        int c = clsS[i];                       // warp-uniform
        const ull* qrow = Q2 + (size_t)c*kQPAD;

        ull a0 = Rsh[c*kD2 + t];
        ull a1 = ffma2x(coef2[c], s[i], 0ULL);
        ull a2 = 0ULL;
        #pragma unroll
        for (int j = 0; j < 7; j++){
            a0 = ffma2x(qrow[3*j+0], pre[3*j+0], a0);
            a1 = ffma2x(qrow[3*j+1], pre[3*j+1], a1);
            a2 = ffma2x(qrow[3*j+2], pre[3*j+2], a2);
        }
        fp[(size_t)i*kD2] = fadd2(fadd2(a0, a1), a2);

        #pragma unroll
        for (int cc = 0; cc < kC; cc++)
            if (cc == c) pre[cc] = fadd2(pre[cc], s[i]);
    }
}

// ===========================================================================
extern "C" void kernel_launch(void* const* d_in, const int* in_sizes, int n_in,
                              void* d_out, int out_size)
{
    const float* P   = (const float*)d_in[0];  // cls_r_prob [C,C]
    const float* src = (const float*)d_in[1];  // source [B,L,D]
    const void*  cls = d_in[2];                // class_idx [B,L]

    float* outF = (float*)d_out;
    const long long fusedElems = (long long)kB*kL*kD;
    float* outS = ((long long)out_size >= 2*fusedElems) ? (outF + fusedElems) : nullptr;

    sum_kernel <<<dim3(kChunks, kB), kT>>>(src, cls, outS);
    scan_kernel<<<kB*kC, kT>>>(P);
    main_kernel<<<dim3(kChunks, kB), kT>>>(P, src, outF);
}

// round 4
// speedup vs baseline: 1.2108x; 1.0714x over previous
#include <cuda_runtime.h>

#define kB 16
#define kL 1444
#define kD 128
#define kD2 64          // float2 lanes per position
#define kC 21
#define kChunks 76
#define kCL 19          // 76*19 == 1444
#define kT 64
#define kQP 22          // padded Q row stride
#define kWaves 4        // 76 = 4*19 scan waves
#define kTRI 171        // 19*18/2 strict-lower triangle entries

typedef unsigned long long ull;

// Device scratch (no allocations allowed)
__device__ float g_cs[kB*kChunks*kC*kD];   // chunk class sums -> exclusive prefix after K2
__device__ float g_tot[kB*kC*kD];          // per-batch class totals
__device__ float g_R[kB*kC*kD];            // R[b][a][d] = sum_c P[c][a]*tot[b][c][d]
__device__ int   g_cls[kB*kL];             // class idx as int32
__device__ unsigned g_cnt[kB];             // per-batch arrival counters (self-resetting)

// ---- packed f32x2 helpers (Blackwell) -------------------------------------
static __device__ __forceinline__ ull fadd2(ull a, ull b){
    ull r; asm("add.rn.f32x2 %0,%1,%2;" : "=l"(r) : "l"(a), "l"(b)); return r;
}
static __device__ __forceinline__ ull ffma2x(ull a, ull b, ull c){
    ull r; asm("fma.rn.f32x2 %0,%1,%2,%3;" : "=l"(r) : "l"(a), "l"(b), "l"(c)); return r;
}
static __device__ __forceinline__ ull dup2(float x){
    ull r; asm("mov.b64 %0,{%1,%1};" : "=l"(r) : "f"(x)); return r;
}
static __device__ __forceinline__ ull ldcg64(const float* p){
    ull r; asm volatile("ld.global.cg.b64 %0,[%1];" : "=l"(r) : "l"(p)); return r;
}
static __device__ __forceinline__ void stcg64(float* p, ull v){
    asm volatile("st.global.cg.b64 [%0],%1;" :: "l"(p), "l"(v));
}

// ===========================================================================
// K0: dtype detection + index conversion (once).
__global__ void __launch_bounds__(128) convert_kernel(const void* __restrict__ cls)
{
    // any 64-bit word > 20 is impossible under int64 layout => int32
    int bad = 0;
    const ull* p64 = (const ull*)cls;
    for (int i = threadIdx.x; i < 256; i += 128)
        if (p64[i] > 20ULL) bad = 1;
    int is32 = __syncthreads_or(bad);

    int i = blockIdx.x * 128 + threadIdx.x;
    if (i < kB*kL)
        g_cls[i] = is32 ? ((const int*)cls)[i]
                        : (int)((const long long*)cls)[i];
}

// ===========================================================================
// K1: per-chunk class sums via thread-private smem scatter + source copy.
__global__ void __launch_bounds__(kT) sum_kernel(const float* __restrict__ src,
                                                 float* __restrict__ outS)
{
    const int t = threadIdx.x;
    const int chunk = blockIdx.x, b = blockIdx.y;

    __shared__ int clsS[kCL];
    __shared__ ull acc[kC*kT];     // [class][thread] -- thread-private columns

    const int posBase = b*kL + chunk*kCL;
    if (t < kCL) clsS[t] = g_cls[posBase + t];
    #pragma unroll
    for (int c = 0; c < kC; c++) acc[c*kT + t] = 0ULL;
    __syncthreads();

    const ull* sp = (const ull*)src + (size_t)posBase*kD2 + t;
    ull s[kCL];
    #pragma unroll
    for (int i = 0; i < kCL; i++) s[i] = sp[(size_t)i*kD2];

    if (outS){
        ull* osp = (ull*)outS + (size_t)posBase*kD2 + t;
        #pragma unroll
        for (int i = 0; i < kCL; i++) osp[(size_t)i*kD2] = s[i];
    }

    #pragma unroll
    for (int i = 0; i < kCL; i++){
        int c = clsS[i];                      // warp-uniform
        acc[c*kT + t] = fadd2(acc[c*kT + t], s[i]);   // private slot, no sync
    }

    float* cs = g_cs + ((size_t)(b*kChunks + chunk)*kC)*kD + 2*t;
    #pragma unroll
    for (int c = 0; c < kC; c++) stcg64(cs + (size_t)c*kD, acc[c*kT + t]);
}

// ===========================================================================
// K2: exclusive scan over chunks per (b,c); last CTA per batch computes R.
__global__ void __launch_bounds__(kT) scan_kernel(const float* __restrict__ P)
{
    const int t = threadIdx.x;
    const int id = blockIdx.x;
    const int b = id / kC, c = id % kC;

    float* base = g_cs + ((size_t)b*kChunks*kC + c)*kD + 2*t;
    const size_t stride = (size_t)kC*kD;

    ull run = 0ULL;
    #pragma unroll
    for (int w = 0; w < kWaves; w++){
        ull v[kCL];
        #pragma unroll
        for (int k = 0; k < kCL; k++) v[k] = ldcg64(base + (size_t)(w*kCL + k)*stride);
        #pragma unroll
        for (int k = 0; k < kCL; k++){
            stcg64(base + (size_t)(w*kCL + k)*stride, run);
            run = fadd2(run, v[k]);
        }
    }
    stcg64(g_tot + ((size_t)b*kC + c)*kD + 2*t, run);

    __threadfence();
    __shared__ int isLast;
    if (t == 0){
        unsigned old = atomicAdd(&g_cnt[b], 1u);
        isLast = (old == (unsigned)(kC - 1));
    }
    __syncthreads();

    if (isLast){
        __threadfence();
        __shared__ float Psh[kC*kC];
        for (int i = t; i < kC*kC; i += kT) Psh[i] = P[i];

        ull tot2[kC];
        #pragma unroll
        for (int cc = 0; cc < kC; cc++)
            tot2[cc] = ldcg64(g_tot + ((size_t)b*kC + cc)*kD + 2*t);
        __syncthreads();

        #pragma unroll
        for (int a = 0; a < kC; a++){
            ull r = 0ULL;
            #pragma unroll
            for (int cc = 0; cc < kC; cc++)
                r = ffma2x(dup2(Psh[cc*kC + a]), tot2[cc], r);
            stcg64(g_R + ((size_t)b*kC + a)*kD + 2*t, r);
        }
        if (t == 0) g_cnt[b] = 0u;   // self-reset for graph replay
    }
}

// ===========================================================================
// K3: fused[i] = QB[c_i] + coef[c_i]*s_i + sum_{j<i} M[i][j]*s_j
//     QB[a] = R[a] + sum_c Q[a,c]*base[c]   (only classes present in chunk)
__global__ void __launch_bounds__(kT) main_kernel(const float* __restrict__ P,
                                                  const float* __restrict__ src,
                                                  float* __restrict__ outF)
{
    const int t = threadIdx.x;
    const int chunk = blockIdx.x, b = blockIdx.y;

    __shared__ ull Q2[kC*kQP];       // dup(P[a][c]-P[c][a])
    __shared__ ull coef2[kC];
    __shared__ ull M2[kTRI];         // triangle coeffs for this chunk
    __shared__ ull QBs[kC*kT];       // per-class combined vector (thread columns)
    __shared__ int clsS[kCL];
    __shared__ int presentS[kC + 1]; // [0]=count, then class list

    for (int idx = t; idx < kC*kC; idx += kT){
        int a = idx / kC, c = idx % kC;
        Q2[a*kQP + c] = dup2(P[a*kC + c] - P[c*kC + a]);
    }
    if (t < kC) coef2[t] = dup2((t != 0 ? 1.0f : 0.0f) - P[t*kC + t]);

    const int posBase = b*kL + chunk*kCL;
    if (t < kCL) clsS[t] = g_cls[posBase + t];
    __syncthreads();

    // triangle matrix M2[tri(i)+j] = Q[c_i, c_j], j < i
    for (int idx = t; idx < kTRI; idx += kT){
        int i = 1;
        while (i*(i+1)/2 <= idx) i++;
        int j = idx - i*(i-1)/2;
        M2[idx] = Q2[clsS[i]*kQP + clsS[j]];
    }

    // compact list of classes present in this chunk (warp-uniform loop bound)
    if (t == 0){
        unsigned mask = 0;
        #pragma unroll
        for (int i = 0; i < kCL; i++) mask |= 1u << clsS[i];
        int n = 0;
        while (mask){ int a = __ffs(mask) - 1; mask &= mask - 1; presentS[1 + n++] = a; }
        presentS[0] = n;
    }

    // preload R into QBs (MLP across all 21 classes)
    const float* Rr = g_R + ((size_t)b*kC)*kD + 2*t;
    #pragma unroll
    for (int a = 0; a < kC; a++) QBs[a*kT + t] = ldcg64(Rr + (size_t)a*kD);

    // base = exclusive chunk-start class sums (registers)
    ull base[kC];
    const float* cs = g_cs + ((size_t)(b*kChunks + chunk)*kC)*kD + 2*t;
    #pragma unroll
    for (int c = 0; c < kC; c++) base[c] = ldcg64(cs + (size_t)c*kD);
    __syncthreads();

    // QB[a] for present classes only
    const int nd = presentS[0];
    for (int k = 0; k < nd; k++){
        int a = presentS[1 + k];             // warp-uniform
        ull r = QBs[a*kT + t];
        #pragma unroll
        for (int c = 0; c < kC; c++)
            r = ffma2x(Q2[a*kQP + c], base[c], r);
        QBs[a*kT + t] = r;                   // own column, no sync needed
    }

    const ull* sp = (const ull*)src + (size_t)posBase*kD2 + t;
    ull* fp = (ull*)outF + (size_t)posBase*kD2 + t;
    ull s[kCL];
    #pragma unroll
    for (int i = 0; i < kCL; i++) s[i] = sp[(size_t)i*kD2];

    #pragma unroll
    for (int i = 0; i < kCL; i++){
        int c = clsS[i];                     // warp-uniform
        ull r = QBs[c*kT + t];
        r = ffma2x(coef2[c], s[i], r);
        const int tb = i*(i-1)/2;
        #pragma unroll
        for (int j = 0; j < i; j++)
            r = ffma2x(M2[tb + j], s[j], r);
        fp[(size_t)i*kD2] = r;
    }
}

// ===========================================================================
extern "C" void kernel_launch(void* const* d_in, const int* in_sizes, int n_in,
                              void* d_out, int out_size)
{
    const float* P   = (const float*)d_in[0];  // cls_r_prob [C,C]
    const float* src = (const float*)d_in[1];  // source [B,L,D]
    const void*  cls = d_in[2];                // class_idx [B,L]

    float* outF = (float*)d_out;
    const long long fusedElems = (long long)kB*kL*kD;
    float* outS = ((long long)out_size >= 2*fusedElems) ? (outF + fusedElems) : nullptr;

    convert_kernel<<<(kB*kL + 127)/128, 128>>>(cls);
    sum_kernel    <<<dim3(kChunks, kB), kT>>>(src, outS);
    scan_kernel   <<<kB*kC, kT>>>(P);
    main_kernel   <<<dim3(kChunks, kB), kT>>>(P, src, outF);
}